// round 1
// baseline (speedup 1.0000x reference)
#include <cuda_runtime.h>
#include <cuda_fp16.h>
#include <math.h>

// ---------------- problem constants ----------------
#define NNODES 2048
#define SEQ    512
#define HID    256
#define NFEAT  9
#define NEDGE  65536
#define NLAY   3
#define STEPA  14

#define H   2048          // GRU hidden = NNODES
#define T   256           // GRU time steps = HID
#define GH  6144          // 3*H

// scan kernel partitioning
#define NBLK 128          // persistent CTAs (<= SM count, co-resident)
#define IPB  16           // hidden units per CTA  (NBLK*IPB == H)
#define RPB  48           // weight rows per CTA (3 gates * IPB)
#define SCAN_THREADS 512
#define SCAN_SMEM (RPB*H*2 + H*4 + 4*RPB*4)   // fp16 weights + h stage + partials

// ---------------- scratch (device globals; no cudaMalloc allowed) ----------------
__device__ float    g_xs[NNODES*SEQ];       // conv output (n, s)
__device__ float    g_h0[NNODES*HID];       // pre-GCN h
__device__ float    g_hagg[NNODES*HID];     // GCN aggregate
__device__ float    g_deg[NNODES];
__device__ float    g_dinv[NNODES];
__device__ float    g_seq[T*H];             // layer input/output sequence (time-major)
__device__ float    g_gi[T*GH];             // precomputed input gates
__device__ __half   g_whh_h[GH*H];          // current layer whh in fp16
__device__ float    g_hbuf[2*H];            // double-buffered hidden state
__device__ unsigned g_bar[T];               // per-step barrier counters

// ---------------- small helpers ----------------
__device__ __forceinline__ void bar_arrive(unsigned* p) {
    asm volatile("red.release.gpu.global.add.u32 [%0], 1;" :: "l"(p) : "memory");
}
__device__ __forceinline__ unsigned bar_ld_acq(const unsigned* p) {
    unsigned v;
    asm volatile("ld.acquire.gpu.global.u32 %0, [%1];" : "=r"(v) : "l"(p) : "memory");
    return v;
}

// ---------------- 1) 1x1 conv over channels ----------------
__global__ void k_conv(const float* __restrict__ x, const float* __restrict__ cw,
                       const float* __restrict__ cb) {
    int i = blockIdx.x * blockDim.x + threadIdx.x;      // over NNODES*SEQ/4
    const int n4 = NNODES * SEQ / 4;
    if (i >= n4) return;
    float b = cb[0];
    float4 acc = make_float4(b, b, b, b);
    const float4* X = (const float4*)x;
#pragma unroll
    for (int f = 0; f < NFEAT; f++) {
        float w = __ldg(&cw[f]);
        float4 v = X[(size_t)f * n4 + i];
        acc.x = fmaf(w, v.x, acc.x); acc.y = fmaf(w, v.y, acc.y);
        acc.z = fmaf(w, v.z, acc.z); acc.w = fmaf(w, v.w, acc.w);
    }
    ((float4*)g_xs)[i] = acc;
}

// ---------------- 2) h0 = xs @ gcn_w   (2048x512)@(512x256) ----------------
__global__ void k_mm_gcn(const float* __restrict__ B /*gcn_w [512][256]*/) {
    __shared__ float As[16][64];
    __shared__ float Bs[16][64];
    const float* A = g_xs;
    int bm = blockIdx.y * 64, bn = blockIdx.x * 64;
    int tid = threadIdx.x;
    int tx = tid & 15, ty = tid >> 4;
    float acc[4][4] = {};
    for (int k0 = 0; k0 < SEQ; k0 += 16) {
        {   // A tile (64x16), transpose into As[k][m]
            int r = tid >> 2, c = (tid & 3) * 4;
            float4 v = *(const float4*)&A[(bm + r) * SEQ + k0 + c];
            As[c+0][r] = v.x; As[c+1][r] = v.y; As[c+2][r] = v.z; As[c+3][r] = v.w;
        }
        for (int i = tid; i < 16 * 64; i += 256) {  // B tile [k][n]
            int r = i >> 6, c = i & 63;
            Bs[r][c] = B[(k0 + r) * HID + bn + c];
        }
        __syncthreads();
#pragma unroll
        for (int kk = 0; kk < 16; kk++) {
            float4 a = *(const float4*)&As[kk][ty * 4];
            float4 b = *(const float4*)&Bs[kk][tx * 4];
            float av[4] = {a.x, a.y, a.z, a.w};
            float bv[4] = {b.x, b.y, b.z, b.w};
#pragma unroll
            for (int i = 0; i < 4; i++)
#pragma unroll
                for (int j = 0; j < 4; j++)
                    acc[i][j] = fmaf(av[i], bv[j], acc[i][j]);
        }
        __syncthreads();
    }
#pragma unroll
    for (int i = 0; i < 4; i++)
#pragma unroll
        for (int j = 0; j < 4; j++)
            g_h0[(bm + ty * 4 + i) * HID + bn + tx * 4 + j] = acc[i][j];
}

// ---------------- 3) GCN: degree / dinv / aggregate / finalize ----------------
__global__ void k_zero1() {
    int i = blockIdx.x * blockDim.x + threadIdx.x;
    int stride = gridDim.x * blockDim.x;
    for (int j = i; j < NNODES * HID; j += stride) g_hagg[j] = 0.0f;
    for (int j = i; j < NNODES; j += stride) g_deg[j] = 1.0f;   // self-loop weight
}

__global__ void k_deg(const int* __restrict__ ei, const float* __restrict__ ew) {
    int e = blockIdx.x * blockDim.x + threadIdx.x;
    if (e < NEDGE) atomicAdd(&g_deg[ei[NEDGE + e]], ew[e]);
}

__global__ void k_dinv() {
    int i = blockIdx.x * blockDim.x + threadIdx.x;
    if (i < NNODES) g_dinv[i] = rsqrtf(fmaxf(g_deg[i], 1e-12f));
}

__global__ void k_agg(const int* __restrict__ ei, const float* __restrict__ ew) {
    int wg = (blockIdx.x * blockDim.x + threadIdx.x) >> 5;
    int lane = threadIdx.x & 31;
    if (wg >= NEDGE) return;
    int row = ei[wg], col = ei[NEDGE + wg];
    float norm = g_dinv[row] * ew[wg] * g_dinv[col];
    const float* hs = g_h0 + (size_t)row * HID;
    float* hd = g_hagg + (size_t)col * HID;
#pragma unroll
    for (int j = 0; j < HID / 32; j++)
        atomicAdd(&hd[lane + 32 * j], norm * hs[lane + 32 * j]);
}

// self-loop + bias + relu + transpose into time-major seq
__global__ void k_fin(const float* __restrict__ gcn_b) {
    int n = blockIdx.x, c = threadIdx.x;     // 256 threads
    float d = g_dinv[n];
    float v = g_hagg[n * HID + c] + d * d * g_h0[n * HID + c] + gcn_b[c];
    v = fmaxf(v, 0.0f);
    g_seq[c * H + n] = v;
}

// ---------------- 4) whh -> fp16 ----------------
__global__ void k_cvt(const float* __restrict__ src) {
    int i = blockIdx.x * blockDim.x + threadIdx.x;
    int stride = gridDim.x * blockDim.x;
    const int n4 = GH * H / 4;
    const float4* s4 = (const float4*)src;
    __half2* d2 = (__half2*)g_whh_h;
    for (int j = i; j < n4; j += stride) {
        float4 v = s4[j];
        d2[2 * j]     = __floats2half2_rn(v.x, v.y);
        d2[2 * j + 1] = __floats2half2_rn(v.z, v.w);
    }
}

// ---------------- 5) gi = seq @ wih.T + bih   (256x6144, K=2048) ----------------
__global__ void k_gi(const float* __restrict__ B /*wih [6144][2048]*/,
                     const float* __restrict__ bih) {
    __shared__ float As[16][64];
    __shared__ float Bs[16][64];
    const float* A = g_seq;                 // [T][H]
    int bn = blockIdx.x * 64, bm = blockIdx.y * 64;
    int tid = threadIdx.x;
    int tx = tid & 15, ty = tid >> 4;
    float acc[4][4] = {};
    for (int k0 = 0; k0 < H; k0 += 16) {
        int r = tid >> 2, c = (tid & 3) * 4;
        float4 v = *(const float4*)&A[(bm + r) * H + k0 + c];
        As[c+0][r] = v.x; As[c+1][r] = v.y; As[c+2][r] = v.z; As[c+3][r] = v.w;
        float4 w = *(const float4*)&B[(size_t)(bn + r) * H + k0 + c];
        Bs[c+0][r] = w.x; Bs[c+1][r] = w.y; Bs[c+2][r] = w.z; Bs[c+3][r] = w.w;
        __syncthreads();
#pragma unroll
        for (int kk = 0; kk < 16; kk++) {
            float4 a = *(const float4*)&As[kk][ty * 4];
            float4 b = *(const float4*)&Bs[kk][tx * 4];
            float av[4] = {a.x, a.y, a.z, a.w};
            float bv[4] = {b.x, b.y, b.z, b.w};
#pragma unroll
            for (int i = 0; i < 4; i++)
#pragma unroll
                for (int j = 0; j < 4; j++)
                    acc[i][j] = fmaf(av[i], bv[j], acc[i][j]);
        }
        __syncthreads();
    }
#pragma unroll
    for (int i = 0; i < 4; i++) {
        int t = bm + ty * 4 + i;
#pragma unroll
        for (int j = 0; j < 4; j++) {
            int g = bn + tx * 4 + j;
            g_gi[t * GH + g] = acc[i][j] + bih[g];
        }
    }
}

// ---------------- 6) zero hidden state + barrier counters ----------------
__global__ void k_zero2() {
    int i = blockIdx.x * blockDim.x + threadIdx.x;
    if (i < 2 * H) g_hbuf[i] = 0.0f;
    if (i < T) g_bar[i] = 0u;
}

// ---------------- 7) persistent GRU scan (the hot kernel) ----------------
// 128 CTAs, each owns 16 hidden units (48 weight rows) resident in SMEM as fp16.
// One global counter-barrier per timestep; h double-buffered in L2.
__global__ void __launch_bounds__(SCAN_THREADS, 1)
k_scan(const float* __restrict__ bhh) {
    extern __shared__ char smem[];
    __half* sw   = (__half*)smem;                       // [RPB][H]
    float*  sh   = (float*)(smem + RPB * H * 2);        // [H]
    float*  spart= sh + H;                              // [4][RPB]

    const int b = blockIdx.x, tid = threadIdx.x;
    const int warp = tid >> 5, lane = tid & 31;
    const int cg = warp & 3, rg = warp >> 2;            // 4 col groups x 4 row groups
    const int colbase = cg * 512 + 8 * lane;            // 8 cols per lane, +256 stride

    // load this CTA's 48 weight rows (fp16) into SMEM
    {
        const int4* W4 = (const int4*)g_whh_h;          // 8 halves per int4
        int4* S4 = (int4*)sw;
        const int per_row = H / 8;                      // 256
        for (int idx = tid; idx < RPB * per_row; idx += SCAN_THREADS) {
            int lr = idx / per_row, c = idx % per_row;
            int grow = (lr >> 4) * H + b * IPB + (lr & 15);
            S4[lr * per_row + c] = W4[(size_t)grow * per_row + c];
        }
    }
    __syncthreads();

#pragma unroll 1
    for (int t = 0; t < T; t++) {
        const int p = t & 1;
        // stage h into SMEM (512 threads x float4 = 2048 floats)
        ((float4*)sh)[tid] = ((const float4*)(g_hbuf + p * H))[tid];
        __syncthreads();

        // register-cache this lane's 16 h values
        float hx[16];
#pragma unroll
        for (int k = 0; k < 2; k++) {
            float4 f0 = *(const float4*)&sh[colbase + 256 * k];
            float4 f1 = *(const float4*)&sh[colbase + 256 * k + 4];
            hx[k*8+0]=f0.x; hx[k*8+1]=f0.y; hx[k*8+2]=f0.z; hx[k*8+3]=f0.w;
            hx[k*8+4]=f1.x; hx[k*8+5]=f1.y; hx[k*8+6]=f1.z; hx[k*8+7]=f1.w;
        }

        // 12 rows x 512-col partial dots
        float acc[12];
#pragma unroll
        for (int r = 0; r < 12; r++) {
            int lr = rg * 12 + r;
            const __half* wr = sw + lr * H + colbase;
            float a = 0.0f;
#pragma unroll
            for (int k = 0; k < 2; k++) {
                uint4 w4 = *(const uint4*)(wr + 256 * k);
                const __half2* hp = (const __half2*)&w4;
#pragma unroll
                for (int m = 0; m < 4; m++) {
                    float2 f = __half22float2(hp[m]);
                    a = fmaf(f.x, hx[k*8 + 2*m],     a);
                    a = fmaf(f.y, hx[k*8 + 2*m + 1], a);
                }
            }
            acc[r] = a;
        }
        // warp reductions, lane 0 publishes partials
#pragma unroll
        for (int r = 0; r < 12; r++) {
            float a = acc[r];
            a += __shfl_xor_sync(0xffffffffu, a, 16);
            a += __shfl_xor_sync(0xffffffffu, a, 8);
            a += __shfl_xor_sync(0xffffffffu, a, 4);
            a += __shfl_xor_sync(0xffffffffu, a, 2);
            a += __shfl_xor_sync(0xffffffffu, a, 1);
            if (lane == 0) spart[cg * RPB + rg * 12 + r] = a;
        }
        __syncthreads();

        // gate math for this CTA's 16 hidden units
        if (tid < IPB) {
            int ii = tid, ig = b * IPB + ii;
            float ghr = 0, ghz = 0, ghn = 0;
#pragma unroll
            for (int c = 0; c < 4; c++) {
                ghr += spart[c * RPB + ii];
                ghz += spart[c * RPB + 16 + ii];
                ghn += spart[c * RPB + 32 + ii];
            }
            ghr += bhh[ig]; ghz += bhh[H + ig]; ghn += bhh[2 * H + ig];
            const float* git = g_gi + (size_t)t * GH;
            float rr = 1.0f / (1.0f + expf(-(git[ig] + ghr)));
            float zz = 1.0f / (1.0f + expf(-(git[H + ig] + ghz)));
            float nn = tanhf(git[2 * H + ig] + rr * ghn);
            float hnew = (1.0f - zz) * nn + zz * sh[ig];
            g_hbuf[(1 - p) * H + ig] = hnew;
            g_seq[t * H + ig] = hnew;
            __threadfence();
        }
        __syncthreads();
        if (tid == 0) {
            bar_arrive(&g_bar[t]);
            while (bar_ld_acq(&g_bar[t]) < NBLK) {}
        }
        __syncthreads();
    }
}

// ---------------- 8) final linear: out[n] = seq[:,n] @ lin_w + lin_b ----------------
__global__ void k_final(const float* __restrict__ lw, const float* __restrict__ lb,
                        float* __restrict__ out) {
    __shared__ float s[T];
    int n = blockIdx.x, tid = threadIdx.x;   // 256 threads
    s[tid] = g_seq[tid * H + n];
    __syncthreads();
    if (tid < STEPA) {
        float a = lb[tid];
#pragma unroll 8
        for (int t = 0; t < T; t++) a = fmaf(s[t], lw[t * STEPA + tid], a);
        out[n * STEPA + tid] = a;
    }
}

// ---------------- launch ----------------
extern "C" void kernel_launch(void* const* d_in, const int* in_sizes, int n_in,
                              void* d_out, int out_size) {
    const float* x      = (const float*)d_in[0];
    const int*   ei     = (const int*)  d_in[1];
    const float* ew     = (const float*)d_in[2];
    const float* cnn_w  = (const float*)d_in[3];
    const float* cnn_b  = (const float*)d_in[4];
    const float* gcn_w  = (const float*)d_in[5];
    const float* gcn_b  = (const float*)d_in[6];
    const float* wih    = (const float*)d_in[7];
    const float* whh    = (const float*)d_in[8];
    const float* bih    = (const float*)d_in[9];
    const float* bhh    = (const float*)d_in[10];
    const float* lin_w  = (const float*)d_in[11];
    const float* lin_b  = (const float*)d_in[12];
    float* out = (float*)d_out;

    cudaFuncSetAttribute(k_scan, cudaFuncAttributeMaxDynamicSharedMemorySize, SCAN_SMEM);

    // preprocessing
    k_conv<<<(NNODES * SEQ / 4 + 255) / 256, 256>>>(x, cnn_w, cnn_b);
    {
        dim3 grid(HID / 64, NNODES / 64);
        k_mm_gcn<<<grid, 256>>>(gcn_w);
    }
    k_zero1<<<512, 256>>>();
    k_deg<<<(NEDGE + 255) / 256, 256>>>(ei, ew);
    k_dinv<<<(NNODES + 255) / 256, 256>>>();
    k_agg<<<NEDGE * 32 / 256, 256>>>(ei, ew);
    k_fin<<<NNODES, HID>>>(gcn_b);

    // 3 GRU layers
    for (int l = 0; l < NLAY; l++) {
        k_cvt<<<512, 256>>>(whh + (size_t)l * GH * H);
        {
            dim3 grid(GH / 64, T / 64);
            k_gi<<<grid, 256>>>(wih + (size_t)l * GH * H, bih + l * GH);
        }
        k_zero2<<<(2 * H + 255) / 256, 256>>>();
        k_scan<<<NBLK, SCAN_THREADS, SCAN_SMEM>>>(bhh + l * GH);
    }

    k_final<<<NNODES, T>>>(lin_w, lin_b, out);
}

// round 2
// speedup vs baseline: 1.3679x; 1.3679x over previous
#include <cuda_runtime.h>
#include <cuda_fp16.h>
#include <math.h>

// ---------------- problem constants ----------------
#define NNODES 2048
#define SEQ    512
#define HID    256
#define NFEAT  9
#define NEDGE  65536
#define NLAY   3
#define STEPA  14

#define H   2048          // GRU hidden = NNODES
#define T   256           // GRU time steps = HID
#define GH  6144          // 3*H

// scan kernel partitioning
#define NBLK 128          // persistent CTAs (<= SM count, co-resident)
#define IPB  16           // hidden units per CTA  (NBLK*IPB == H)
#define RPB  48           // weight rows per CTA (3 gates * IPB)
#define SCAN_THREADS 512
#define SCAN_SMEM (RPB*H*2 + 4*RPB*4)   // fp16 weights + partials

// ---------------- scratch (device globals; no cudaMalloc allowed) ----------------
__device__ float    g_xs[NNODES*SEQ];       // conv output (n, s)
__device__ float    g_h0[NNODES*HID];       // pre-GCN h
__device__ float    g_hagg[NNODES*HID];     // GCN aggregate
__device__ float    g_deg[NNODES];
__device__ float    g_dinv[NNODES];
__device__ float    g_seq[T*H];             // layer input/output sequence (time-major)
__device__ float    g_gi[T*GH];             // precomputed input gates
__device__ float    g_hbuf[2*H];            // double-buffered hidden state
__device__ unsigned g_bar[T];               // per-step barrier counters

// ---------------- small helpers ----------------
__device__ __forceinline__ void bar_arrive(unsigned* p) {
    asm volatile("red.release.gpu.global.add.u32 [%0], 1;" :: "l"(p) : "memory");
}
__device__ __forceinline__ unsigned bar_ld_acq(const unsigned* p) {
    unsigned v;
    asm volatile("ld.acquire.gpu.global.u32 %0, [%1];" : "=r"(v) : "l"(p) : "memory");
    return v;
}
__device__ __forceinline__ void mma16816(float* d, const unsigned* a, const unsigned* b) {
    asm volatile("mma.sync.aligned.m16n8k16.row.col.f32.f16.f16.f32 "
                 "{%0,%1,%2,%3},{%4,%5,%6,%7},{%8,%9},{%0,%1,%2,%3};"
                 : "+f"(d[0]), "+f"(d[1]), "+f"(d[2]), "+f"(d[3])
                 : "r"(a[0]), "r"(a[1]), "r"(a[2]), "r"(a[3]),
                   "r"(b[0]), "r"(b[1]));
}

// ---------------- 1) 1x1 conv over channels ----------------
__global__ void k_conv(const float* __restrict__ x, const float* __restrict__ cw,
                       const float* __restrict__ cb) {
    int i = blockIdx.x * blockDim.x + threadIdx.x;      // over NNODES*SEQ/4
    const int n4 = NNODES * SEQ / 4;
    if (i >= n4) return;
    float b = cb[0];
    float4 acc = make_float4(b, b, b, b);
    const float4* X = (const float4*)x;
#pragma unroll
    for (int f = 0; f < NFEAT; f++) {
        float w = __ldg(&cw[f]);
        float4 v = X[(size_t)f * n4 + i];
        acc.x = fmaf(w, v.x, acc.x); acc.y = fmaf(w, v.y, acc.y);
        acc.z = fmaf(w, v.z, acc.z); acc.w = fmaf(w, v.w, acc.w);
    }
    ((float4*)g_xs)[i] = acc;
}

// ---------------- 2) h0 = xs @ gcn_w   (2048x512)@(512x256) ----------------
__global__ void k_mm_gcn(const float* __restrict__ B /*gcn_w [512][256]*/) {
    __shared__ float As[16][64];
    __shared__ float Bs[16][64];
    const float* A = g_xs;
    int bm = blockIdx.y * 64, bn = blockIdx.x * 64;
    int tid = threadIdx.x;
    int tx = tid & 15, ty = tid >> 4;
    float acc[4][4] = {};
    for (int k0 = 0; k0 < SEQ; k0 += 16) {
        {   // A tile (64x16), transpose into As[k][m]
            int r = tid >> 2, c = (tid & 3) * 4;
            float4 v = *(const float4*)&A[(bm + r) * SEQ + k0 + c];
            As[c+0][r] = v.x; As[c+1][r] = v.y; As[c+2][r] = v.z; As[c+3][r] = v.w;
        }
        for (int i = tid; i < 16 * 64; i += 256) {  // B tile [k][n]
            int r = i >> 6, c = i & 63;
            Bs[r][c] = B[(k0 + r) * HID + bn + c];
        }
        __syncthreads();
#pragma unroll
        for (int kk = 0; kk < 16; kk++) {
            float4 a = *(const float4*)&As[kk][ty * 4];
            float4 b = *(const float4*)&Bs[kk][tx * 4];
            float av[4] = {a.x, a.y, a.z, a.w};
            float bv[4] = {b.x, b.y, b.z, b.w};
#pragma unroll
            for (int i = 0; i < 4; i++)
#pragma unroll
                for (int j = 0; j < 4; j++)
                    acc[i][j] = fmaf(av[i], bv[j], acc[i][j]);
        }
        __syncthreads();
    }
#pragma unroll
    for (int i = 0; i < 4; i++)
#pragma unroll
        for (int j = 0; j < 4; j++)
            g_h0[(bm + ty * 4 + i) * HID + bn + tx * 4 + j] = acc[i][j];
}

// ---------------- 3) GCN: degree / dinv / aggregate / finalize ----------------
__global__ void k_zero1() {
    int i = blockIdx.x * blockDim.x + threadIdx.x;
    int stride = gridDim.x * blockDim.x;
    for (int j = i; j < NNODES * HID; j += stride) g_hagg[j] = 0.0f;
    for (int j = i; j < NNODES; j += stride) g_deg[j] = 1.0f;   // self-loop weight
}

__global__ void k_deg(const int* __restrict__ ei, const float* __restrict__ ew) {
    int e = blockIdx.x * blockDim.x + threadIdx.x;
    if (e < NEDGE) atomicAdd(&g_deg[ei[NEDGE + e]], ew[e]);
}

__global__ void k_dinv() {
    int i = blockIdx.x * blockDim.x + threadIdx.x;
    if (i < NNODES) g_dinv[i] = rsqrtf(fmaxf(g_deg[i], 1e-12f));
}

__global__ void k_agg(const int* __restrict__ ei, const float* __restrict__ ew) {
    int wg = (blockIdx.x * blockDim.x + threadIdx.x) >> 5;
    int lane = threadIdx.x & 31;
    if (wg >= NEDGE) return;
    int row = ei[wg], col = ei[NEDGE + wg];
    float norm = g_dinv[row] * ew[wg] * g_dinv[col];
    const float* hs = g_h0 + (size_t)row * HID;
    float* hd = g_hagg + (size_t)col * HID;
#pragma unroll
    for (int j = 0; j < HID / 32; j++)
        atomicAdd(&hd[lane + 32 * j], norm * hs[lane + 32 * j]);
}

// self-loop + bias + relu + transpose into time-major seq
__global__ void k_fin(const float* __restrict__ gcn_b) {
    int n = blockIdx.x, c = threadIdx.x;     // 256 threads
    float d = g_dinv[n];
    float v = g_hagg[n * HID + c] + d * d * g_h0[n * HID + c] + gcn_b[c];
    v = fmaxf(v, 0.0f);
    g_seq[c * H + n] = v;
}

// ---------------- 4) gi = seq @ wih.T + bih  via fp16 tensor cores ----------------
// C[256][6144], K=2048. Tiles: BM=64, BN=128, BK=64. 256 threads = 8 warps (2Mx4N),
// warp tile 32x32 = 2x4 m16n8k16 mma. fp32 inputs converted to fp16 on tile load.
#define GI_LD 72   // padded halves per SMEM row (bank-conflict-free)
__global__ void __launch_bounds__(256) k_gi(const float* __restrict__ B,
                                            const float* __restrict__ bih) {
    __shared__ __half sA[64 * GI_LD];
    __shared__ __half sB[128 * GI_LD];
    const int bm = blockIdx.y * 64, bn = blockIdx.x * 128;
    const int tid = threadIdx.x, lane = tid & 31, warp = tid >> 5;
    const int wm = warp >> 2, wn = warp & 3;
    float acc[2][4][4] = {};

    for (int k0 = 0; k0 < H; k0 += 64) {
#pragma unroll
        for (int i = 0; i < 4; i++) {                       // A tile 64x64
            int idx = tid + i * 256;
            int r = idx >> 4, c4 = idx & 15;
            float4 v = *(const float4*)&g_seq[(bm + r) * H + k0 + c4 * 4];
            *(__half2*)&sA[r * GI_LD + c4 * 4]     = __floats2half2_rn(v.x, v.y);
            *(__half2*)&sA[r * GI_LD + c4 * 4 + 2] = __floats2half2_rn(v.z, v.w);
        }
#pragma unroll
        for (int i = 0; i < 8; i++) {                       // B tile 128x64
            int idx = tid + i * 256;
            int r = idx >> 4, c4 = idx & 15;
            float4 v = *(const float4*)&B[(size_t)(bn + r) * H + k0 + c4 * 4];
            *(__half2*)&sB[r * GI_LD + c4 * 4]     = __floats2half2_rn(v.x, v.y);
            *(__half2*)&sB[r * GI_LD + c4 * 4 + 2] = __floats2half2_rn(v.z, v.w);
        }
        __syncthreads();
#pragma unroll
        for (int ks = 0; ks < 4; ks++) {
            unsigned a[2][4], b[4][2];
#pragma unroll
            for (int mt = 0; mt < 2; mt++) {
                int r = wm * 32 + mt * 16 + (lane >> 2);
                int c = ks * 16 + (lane & 3) * 2;
                a[mt][0] = *(const unsigned*)&sA[r * GI_LD + c];
                a[mt][1] = *(const unsigned*)&sA[(r + 8) * GI_LD + c];
                a[mt][2] = *(const unsigned*)&sA[r * GI_LD + c + 8];
                a[mt][3] = *(const unsigned*)&sA[(r + 8) * GI_LD + c + 8];
            }
#pragma unroll
            for (int nt = 0; nt < 4; nt++) {
                int r = wn * 32 + nt * 8 + (lane >> 2);
                int c = ks * 16 + (lane & 3) * 2;
                b[nt][0] = *(const unsigned*)&sB[r * GI_LD + c];
                b[nt][1] = *(const unsigned*)&sB[r * GI_LD + c + 8];
            }
#pragma unroll
            for (int mt = 0; mt < 2; mt++)
#pragma unroll
                for (int nt = 0; nt < 4; nt++)
                    mma16816(acc[mt][nt], a[mt], b[nt]);
        }
        __syncthreads();
    }
#pragma unroll
    for (int mt = 0; mt < 2; mt++) {
        int r0 = bm + wm * 32 + mt * 16 + (lane >> 2);
#pragma unroll
        for (int nt = 0; nt < 4; nt++) {
            int g = bn + wn * 32 + nt * 8 + (lane & 3) * 2;
            float2 bb = *(const float2*)&bih[g];
            float* c4 = acc[mt][nt];
            *(float2*)&g_gi[r0 * GH + g]       = make_float2(c4[0] + bb.x, c4[1] + bb.y);
            *(float2*)&g_gi[(r0 + 8) * GH + g] = make_float2(c4[2] + bb.x, c4[3] + bb.y);
        }
    }
}

// ---------------- 5) zero hidden state + barrier counters ----------------
__global__ void k_zero2() {
    int i = blockIdx.x * blockDim.x + threadIdx.x;
    if (i < 2 * H) g_hbuf[i] = 0.0f;
    if (i < T) g_bar[i] = 0u;
}

// ---------------- 6) persistent GRU scan (the hot kernel) ----------------
// 128 CTAs, each owns 16 hidden units (48 weight rows) resident in SMEM as fp16
// (converted from fp32 on the one-time fill). One gpu-scope counter-barrier per
// timestep; h double-buffered in L2; h read directly via coalesced LDG.
__global__ void __launch_bounds__(SCAN_THREADS, 1)
k_scan(const float* __restrict__ whh, const float* __restrict__ bhh) {
    extern __shared__ char smem[];
    __half* sw    = (__half*)smem;                       // [RPB][H]
    float*  spart = (float*)(smem + RPB * H * 2);        // [4][RPB]

    const int b = blockIdx.x, tid = threadIdx.x;
    const int warp = tid >> 5, lane = tid & 31;
    const int cg = warp & 3, rg = warp >> 2;             // 4 col groups x 4 row groups
    const int colbase = cg * 512 + 8 * lane;             // 8 cols per lane, +256 stride

    // one-time: load + convert this CTA's 48 weight rows into SMEM fp16
    {
        const int per4 = H / 4;                          // 512 float4 per row
        for (int idx = tid; idx < RPB * per4; idx += SCAN_THREADS) {
            int lr = idx / per4, c = idx % per4;
            int grow = (lr >> 4) * H + b * IPB + (lr & 15);
            float4 v = *(const float4*)&whh[(size_t)grow * H + c * 4];
            *(__half2*)&sw[lr * H + c * 4]     = __floats2half2_rn(v.x, v.y);
            *(__half2*)&sw[lr * H + c * 4 + 2] = __floats2half2_rn(v.z, v.w);
        }
    }
    // per-CTA constant gate biases
    float bR = 0, bZ = 0, bN = 0;
    if (tid < IPB) {
        int ig = b * IPB + tid;
        bR = bhh[ig]; bZ = bhh[H + ig]; bN = bhh[2 * H + ig];
    }
    __syncthreads();

#pragma unroll 1
    for (int t = 0; t < T; t++) {
        const int p = t & 1;
        const float* hb = g_hbuf + p * H;

        // prefetch this step's input gates + own old h (gate threads only)
        float gir = 0, giz = 0, gin = 0, hold = 0;
        if (tid < IPB) {
            const float* git = g_gi + (size_t)t * GH;
            int ig = b * IPB + tid;
            gir = git[ig]; giz = git[H + ig]; gin = git[2 * H + ig];
            hold = hb[ig];
        }

        // register-cache this lane's 16 h values (coalesced LDG from L2)
        float hx[16];
        {
            float4 f0 = *(const float4*)&hb[colbase];
            float4 f1 = *(const float4*)&hb[colbase + 4];
            float4 f2 = *(const float4*)&hb[colbase + 256];
            float4 f3 = *(const float4*)&hb[colbase + 260];
            hx[0]=f0.x; hx[1]=f0.y; hx[2]=f0.z; hx[3]=f0.w;
            hx[4]=f1.x; hx[5]=f1.y; hx[6]=f1.z; hx[7]=f1.w;
            hx[8]=f2.x; hx[9]=f2.y; hx[10]=f2.z; hx[11]=f2.w;
            hx[12]=f3.x; hx[13]=f3.y; hx[14]=f3.z; hx[15]=f3.w;
        }

        // 12 rows x 512-col partial dots
        float acc[12];
#pragma unroll
        for (int r = 0; r < 12; r++) {
            int lr = rg * 12 + r;
            const __half* wr = sw + lr * H + colbase;
            float a = 0.0f;
#pragma unroll
            for (int k = 0; k < 2; k++) {
                uint4 w4 = *(const uint4*)(wr + 256 * k);
                const __half2* hp = (const __half2*)&w4;
#pragma unroll
                for (int m = 0; m < 4; m++) {
                    float2 f = __half22float2(hp[m]);
                    a = fmaf(f.x, hx[k*8 + 2*m],     a);
                    a = fmaf(f.y, hx[k*8 + 2*m + 1], a);
                }
            }
            acc[r] = a;
        }
        // warp reductions, lane 0 publishes partials
#pragma unroll
        for (int r = 0; r < 12; r++) {
            float a = acc[r];
            a += __shfl_xor_sync(0xffffffffu, a, 16);
            a += __shfl_xor_sync(0xffffffffu, a, 8);
            a += __shfl_xor_sync(0xffffffffu, a, 4);
            a += __shfl_xor_sync(0xffffffffu, a, 2);
            a += __shfl_xor_sync(0xffffffffu, a, 1);
            if (lane == 0) spart[cg * RPB + rg * 12 + r] = a;
        }
        __syncthreads();

        // gate math for this CTA's 16 hidden units
        if (tid < IPB) {
            int ii = tid, ig = b * IPB + ii;
            float ghr = 0, ghz = 0, ghn = 0;
#pragma unroll
            for (int c = 0; c < 4; c++) {
                ghr += spart[c * RPB + ii];
                ghz += spart[c * RPB + 16 + ii];
                ghn += spart[c * RPB + 32 + ii];
            }
            float rr = 1.0f / (1.0f + expf(-(gir + ghr + bR)));
            float zz = 1.0f / (1.0f + expf(-(giz + ghz + bZ)));
            float nn = tanhf(gin + rr * (ghn + bN));
            float hnew = (1.0f - zz) * nn + zz * hold;
            g_hbuf[(1 - p) * H + ig] = hnew;
            g_seq[t * H + ig] = hnew;
        }
        __syncthreads();
        if (tid == 0) {
            bar_arrive(&g_bar[t]);               // release: orders the h writes
            while (bar_ld_acq(&g_bar[t]) < NBLK) {}
        }
        __syncthreads();
    }
}

// ---------------- 7) final linear: out[n] = seq[:,n] @ lin_w + lin_b ----------------
__global__ void k_final(const float* __restrict__ lw, const float* __restrict__ lb,
                        float* __restrict__ out) {
    __shared__ float s[T];
    int n = blockIdx.x, tid = threadIdx.x;   // 256 threads
    s[tid] = g_seq[tid * H + n];
    __syncthreads();
    if (tid < STEPA) {
        float a = lb[tid];
#pragma unroll 8
        for (int t = 0; t < T; t++) a = fmaf(s[t], lw[t * STEPA + tid], a);
        out[n * STEPA + tid] = a;
    }
}

// ---------------- launch ----------------
extern "C" void kernel_launch(void* const* d_in, const int* in_sizes, int n_in,
                              void* d_out, int out_size) {
    const float* x      = (const float*)d_in[0];
    const int*   ei     = (const int*)  d_in[1];
    const float* ew     = (const float*)d_in[2];
    const float* cnn_w  = (const float*)d_in[3];
    const float* cnn_b  = (const float*)d_in[4];
    const float* gcn_w  = (const float*)d_in[5];
    const float* gcn_b  = (const float*)d_in[6];
    const float* wih    = (const float*)d_in[7];
    const float* whh    = (const float*)d_in[8];
    const float* bih    = (const float*)d_in[9];
    const float* bhh    = (const float*)d_in[10];
    const float* lin_w  = (const float*)d_in[11];
    const float* lin_b  = (const float*)d_in[12];
    float* out = (float*)d_out;

    cudaFuncSetAttribute(k_scan, cudaFuncAttributeMaxDynamicSharedMemorySize, SCAN_SMEM);

    // preprocessing
    k_conv<<<(NNODES * SEQ / 4 + 255) / 256, 256>>>(x, cnn_w, cnn_b);
    {
        dim3 grid(HID / 64, NNODES / 64);
        k_mm_gcn<<<grid, 256>>>(gcn_w);
    }
    k_zero1<<<512, 256>>>();
    k_deg<<<(NEDGE + 255) / 256, 256>>>(ei, ew);
    k_dinv<<<(NNODES + 255) / 256, 256>>>();
    k_agg<<<NEDGE * 32 / 256, 256>>>(ei, ew);
    k_fin<<<NNODES, HID>>>(gcn_b);

    // 3 GRU layers
    for (int l = 0; l < NLAY; l++) {
        {
            dim3 grid(GH / 128, T / 64);
            k_gi<<<grid, 256>>>(wih + (size_t)l * GH * H, bih + l * GH);
        }
        k_zero2<<<(2 * H + 255) / 256, 256>>>();
        k_scan<<<NBLK, SCAN_THREADS, SCAN_SMEM>>>(whh + (size_t)l * GH * H,
                                                  bhh + l * GH);
    }

    k_final<<<NNODES, T>>>(lin_w, lin_b, out);
}

// round 4
// speedup vs baseline: 1.6435x; 1.2015x over previous
#include <cuda_runtime.h>
#include <cuda_fp16.h>
#include <math.h>

// ---------------- problem constants ----------------
#define NNODES 2048
#define SEQ    512
#define HID    256
#define NFEAT  9
#define NEDGE  65536
#define NLAY   3
#define STEPA  14

#define H   2048          // GRU hidden = NNODES
#define T   256           // GRU time steps = HID
#define GH  6144          // 3*H

#define NBLK 128          // persistent CTAs (co-resident)
#define IPB  16           // hidden units per CTA
#define SCAN_THREADS 512
#define PRE_THREADS  512

// ---------------- scratch (device globals; no cudaMalloc allowed) ----------------
__device__ float    g_xs[NNODES*SEQ];       // conv output (n, s)
__device__ float    g_h0[NNODES*HID];       // pre-GCN h
__device__ float    g_hagg[NNODES*HID];     // GCN aggregate
__device__ float    g_deg[NNODES];
__device__ float    g_dinv[NNODES];
__device__ float    g_seq[T*H];             // layer input/output sequence (time-major)
__device__ float    g_gi[T*GH];             // precomputed input gates
__device__ __align__(16) __half g_hh[2*H];  // double-buffered hidden state (fp16)
__device__ unsigned g_bar[T];               // per-step barrier counters (scan)
__device__ unsigned g_pbar[8];              // phase barrier counters (preproc)

// ---------------- small helpers ----------------
__device__ __forceinline__ void bar_arrive(unsigned* p) {
    asm volatile("red.release.gpu.global.add.u32 [%0], 1;" :: "l"(p) : "memory");
}
__device__ __forceinline__ unsigned bar_ld_acq(const unsigned* p) {
    unsigned v;
    asm volatile("ld.acquire.gpu.global.u32 %0, [%1];" : "=r"(v) : "l"(p) : "memory");
    return v;
}
__device__ __forceinline__ void gbar(unsigned* ctr) {
    __syncthreads();
    if (threadIdx.x == 0) {
        bar_arrive(ctr);
        while (bar_ld_acq(ctr) < NBLK) {}
    }
    __syncthreads();
}
__device__ __forceinline__ void mma16816(float* d, const unsigned* a, const unsigned* b) {
    asm volatile("mma.sync.aligned.m16n8k16.row.col.f32.f16.f16.f32 "
                 "{%0,%1,%2,%3},{%4,%5,%6,%7},{%8,%9},{%0,%1,%2,%3};"
                 : "+f"(d[0]), "+f"(d[1]), "+f"(d[2]), "+f"(d[3])
                 : "r"(a[0]), "r"(a[1]), "r"(a[2]), "r"(a[3]),
                   "r"(b[0]), "r"(b[1]));
}
__device__ __forceinline__ unsigned pack_h2(float x, float y) {
    __half2 h = __floats2half2_rn(x, y);
    return *(unsigned*)&h;
}

// ================= 1) fused preprocessing (persistent, 128 CTAs) =================
// P0 conv+zero -> P1 gcn-matmul + degree -> P2 dinv -> P3 edge aggregate -> P4 finalize
__global__ void __launch_bounds__(PRE_THREADS)
k_pre(const float* __restrict__ x,  const float* __restrict__ cw,
      const float* __restrict__ cb, const int*   __restrict__ ei,
      const float* __restrict__ ew, const float* __restrict__ gw,
      const float* __restrict__ gb) {
    __shared__ float As[16][64];
    __shared__ float Bs[16][68];   // 68*4=272B row stride: 16B-aligned rows, pad vs conflicts
    const int b = blockIdx.x, tid = threadIdx.x;
    const int gt = b * PRE_THREADS + tid;
    const int GT = NBLK * PRE_THREADS;            // 65536

    // ---- P0: 1x1 conv + zero hagg + deg=1 ----
    {
        float bias = cb[0];
        float w[NFEAT];
#pragma unroll
        for (int f = 0; f < NFEAT; f++) w[f] = cw[f];
        const int n4 = NNODES * SEQ / 4;
        const float4* X = (const float4*)x;
        for (int i = gt; i < n4; i += GT) {
            float4 acc = make_float4(bias, bias, bias, bias);
#pragma unroll
            for (int f = 0; f < NFEAT; f++) {
                float4 v = X[(size_t)f * n4 + i];
                acc.x = fmaf(w[f], v.x, acc.x); acc.y = fmaf(w[f], v.y, acc.y);
                acc.z = fmaf(w[f], v.z, acc.z); acc.w = fmaf(w[f], v.w, acc.w);
            }
            ((float4*)g_xs)[i] = acc;
        }
        float4 z4 = make_float4(0.f, 0.f, 0.f, 0.f);
        for (int i = gt; i < NNODES * HID / 4; i += GT) ((float4*)g_hagg)[i] = z4;
        for (int i = gt; i < NNODES; i += GT) g_deg[i] = 1.0f;
    }
    gbar(&g_pbar[0]);

    // ---- P1: degree atomics + h0 = xs @ gcn_w (one 64x64 tile per CTA) ----
    for (int e = gt; e < NEDGE; e += GT)
        atomicAdd(&g_deg[ei[NEDGE + e]], ew[e]);
    {
        const int bm = (b >> 2) * 64, bn = (b & 3) * 64;
        const int tx = tid & 15, ty = tid >> 4;
        float acc[2][4] = {};
        for (int k0 = 0; k0 < SEQ; k0 += 16) {
            {   // A: 64 rows x 16 k, transposed into As[k][m]
                int ar = tid >> 3, ac = (tid & 7) * 2;
                float2 v = *(const float2*)&g_xs[(bm + ar) * SEQ + k0 + ac];
                As[ac][ar] = v.x; As[ac + 1][ar] = v.y;
            }
            {   // B: 16 k x 64 n
                int br = tid >> 5, bc = (tid & 31) * 2;
                float2 v = *(const float2*)&gw[(k0 + br) * HID + bn + bc];
                Bs[br][bc] = v.x; Bs[br][bc + 1] = v.y;
            }
            __syncthreads();
#pragma unroll
            for (int kk = 0; kk < 16; kk++) {
                float a0 = As[kk][ty * 2], a1 = As[kk][ty * 2 + 1];
                float4 bb = *(const float4*)&Bs[kk][tx * 4];
                acc[0][0] = fmaf(a0, bb.x, acc[0][0]); acc[0][1] = fmaf(a0, bb.y, acc[0][1]);
                acc[0][2] = fmaf(a0, bb.z, acc[0][2]); acc[0][3] = fmaf(a0, bb.w, acc[0][3]);
                acc[1][0] = fmaf(a1, bb.x, acc[1][0]); acc[1][1] = fmaf(a1, bb.y, acc[1][1]);
                acc[1][2] = fmaf(a1, bb.z, acc[1][2]); acc[1][3] = fmaf(a1, bb.w, acc[1][3]);
            }
            __syncthreads();
        }
#pragma unroll
        for (int i = 0; i < 2; i++)
#pragma unroll
            for (int j = 0; j < 4; j++)
                g_h0[(bm + ty * 2 + i) * HID + bn + tx * 4 + j] = acc[i][j];
    }
    gbar(&g_pbar[1]);

    // ---- P2: dinv ----
    for (int i = gt; i < NNODES; i += GT)
        g_dinv[i] = rsqrtf(fmaxf(g_deg[i], 1e-12f));
    gbar(&g_pbar[2]);

    // ---- P3: edge aggregation (one warp -> 32 edges) ----
    {
        const int gw2 = gt >> 5, lane = tid & 31;
        for (int e = gw2 * 32; e < gw2 * 32 + 32; e++) {
            int row = ei[e], col = ei[NEDGE + e];
            float norm = g_dinv[row] * ew[e] * g_dinv[col];
            const float* hs = g_h0 + (size_t)row * HID;
            float* hd = g_hagg + (size_t)col * HID;
#pragma unroll
            for (int j = 0; j < HID / 32; j++)
                atomicAdd(&hd[lane + 32 * j], norm * hs[lane + 32 * j]);
        }
    }
    gbar(&g_pbar[3]);

    // ---- P4: self-loop + bias + relu + transpose into g_seq ----
    for (int i = gt; i < NNODES * HID; i += GT) {
        int n = i & (NNODES - 1), c = i >> 11;
        float d = g_dinv[n];
        float v = g_hagg[n * HID + c] + d * d * g_h0[n * HID + c] + gb[c];
        g_seq[c * H + n] = fmaxf(v, 0.0f);
    }
}

// ---------------- 2) gi = seq @ wih.T + bih  via fp16 tensor cores ----------------
#define GI_LD 72
__global__ void __launch_bounds__(256) k_gi(const float* __restrict__ B,
                                            const float* __restrict__ bih) {
    __shared__ alignas(16) __half sA[64 * GI_LD];
    __shared__ alignas(16) __half sB[128 * GI_LD];
    const int bm = blockIdx.y * 64, bn = blockIdx.x * 128;
    const int tid = threadIdx.x, lane = tid & 31, warp = tid >> 5;
    const int wm = warp >> 2, wn = warp & 3;
    float acc[2][4][4] = {};

    for (int k0 = 0; k0 < H; k0 += 64) {
#pragma unroll
        for (int i = 0; i < 4; i++) {                       // A tile 64x64
            int idx = tid + i * 256;
            int r = idx >> 4, c4 = idx & 15;
            float4 v = *(const float4*)&g_seq[(bm + r) * H + k0 + c4 * 4];
            *(__half2*)&sA[r * GI_LD + c4 * 4]     = __floats2half2_rn(v.x, v.y);
            *(__half2*)&sA[r * GI_LD + c4 * 4 + 2] = __floats2half2_rn(v.z, v.w);
        }
#pragma unroll
        for (int i = 0; i < 8; i++) {                       // B tile 128x64
            int idx = tid + i * 256;
            int r = idx >> 4, c4 = idx & 15;
            float4 v = *(const float4*)&B[(size_t)(bn + r) * H + k0 + c4 * 4];
            *(__half2*)&sB[r * GI_LD + c4 * 4]     = __floats2half2_rn(v.x, v.y);
            *(__half2*)&sB[r * GI_LD + c4 * 4 + 2] = __floats2half2_rn(v.z, v.w);
        }
        __syncthreads();
#pragma unroll
        for (int ks = 0; ks < 4; ks++) {
            unsigned a[2][4], b[4][2];
#pragma unroll
            for (int mt = 0; mt < 2; mt++) {
                int r = wm * 32 + mt * 16 + (lane >> 2);
                int c = ks * 16 + (lane & 3) * 2;
                a[mt][0] = *(const unsigned*)&sA[r * GI_LD + c];
                a[mt][1] = *(const unsigned*)&sA[(r + 8) * GI_LD + c];
                a[mt][2] = *(const unsigned*)&sA[r * GI_LD + c + 8];
                a[mt][3] = *(const unsigned*)&sA[(r + 8) * GI_LD + c + 8];
            }
#pragma unroll
            for (int nt = 0; nt < 4; nt++) {
                int r = wn * 32 + nt * 8 + (lane >> 2);
                int c = ks * 16 + (lane & 3) * 2;
                b[nt][0] = *(const unsigned*)&sB[r * GI_LD + c];
                b[nt][1] = *(const unsigned*)&sB[r * GI_LD + c + 8];
            }
#pragma unroll
            for (int mt = 0; mt < 2; mt++)
#pragma unroll
                for (int nt = 0; nt < 4; nt++)
                    mma16816(acc[mt][nt], a[mt], b[nt]);
        }
        __syncthreads();
    }
#pragma unroll
    for (int mt = 0; mt < 2; mt++) {
        int r0 = bm + wm * 32 + mt * 16 + (lane >> 2);
#pragma unroll
        for (int nt = 0; nt < 4; nt++) {
            int g = bn + wn * 32 + nt * 8 + (lane & 3) * 2;
            float2 bb = *(const float2*)&bih[g];
            float* c4 = acc[mt][nt];
            *(float2*)&g_gi[r0 * GH + g]       = make_float2(c4[0] + bb.x, c4[1] + bb.y);
            *(float2*)&g_gi[(r0 + 8) * GH + g] = make_float2(c4[2] + bb.x, c4[3] + bb.y);
        }
    }
}

// ---------------- 3) zero h / barrier counters ----------------
__global__ void k_zero2() {
    int i = blockIdx.x * blockDim.x + threadIdx.x;
    if (i < 2 * H) g_hh[i] = __float2half(0.0f);
    if (i < T) g_bar[i] = 0u;
    if (i < 8) g_pbar[i] = 0u;
}

// ---------------- 4) persistent GRU scan — HMMA, weights in registers ----------------
// 128 CTAs x 512 thr. Each CTA owns 16 hidden units (48 rows of whh = 3 gates x 16).
// Weights live as mma.m16n8k16 A-fragments in registers (96 regs/thread).
// Per step: stage h(fp16) to SMEM -> 24 HMMA/warp (B = h broadcast) -> cross-warp
// reduce 48 partials -> gate math by 16 threads -> gpu-scope counter barrier.
__global__ void __launch_bounds__(SCAN_THREADS, 1)
k_scan(const float* __restrict__ whh, const float* __restrict__ bhh) {
    __shared__ alignas(16) __half sh[H];
    __shared__ float spart[16][48];

    const int b = blockIdx.x, tid = threadIdx.x;
    const int warp = tid >> 5, lane = tid & 31;
    const int qid = lane >> 2, tg = lane & 3;
    const int kbase = warp * 128;                 // this warp's K range (128 cols)

    // ---- one-time: load this thread's A fragments (fp16) ----
    unsigned aw[8][3][4];
    {
        const int r0 = b * IPB + qid;             // rows r0, r0+8 within each gate
#pragma unroll
        for (int kt = 0; kt < 8; kt++) {
            const int c = kbase + kt * 16 + tg * 2;
#pragma unroll
            for (int g = 0; g < 3; g++) {
                const float* W0 = whh + (size_t)(g * H + r0) * H;
                const float* W1 = W0 + 8 * (size_t)H;
                float2 v;
                v = *(const float2*)(W0 + c);     aw[kt][g][0] = pack_h2(v.x, v.y);
                v = *(const float2*)(W1 + c);     aw[kt][g][1] = pack_h2(v.x, v.y);
                v = *(const float2*)(W0 + c + 8); aw[kt][g][2] = pack_h2(v.x, v.y);
                v = *(const float2*)(W1 + c + 8); aw[kt][g][3] = pack_h2(v.x, v.y);
            }
        }
    }
    float hold = 0.0f;                            // own h (gate threads only)

#pragma unroll 1
    for (int t = 0; t < T; t++) {
        const int p = t & 1;
        // stage h into SMEM (L2 read: other SMs wrote it)
        {
            uint2 hv = __ldcg((const uint2*)(g_hh + p * H) + tid);
            *((uint2*)sh + tid) = hv;
        }
        __syncthreads();

        float d[3][4];
#pragma unroll
        for (int g = 0; g < 3; g++) { d[g][0] = d[g][1] = d[g][2] = d[g][3] = 0.f; }

#pragma unroll
        for (int kt = 0; kt < 8; kt++) {
            unsigned bb[2];
            bb[0] = *(const unsigned*)&sh[kbase + kt * 16 + tg * 2];
            bb[1] = *(const unsigned*)&sh[kbase + kt * 16 + tg * 2 + 8];
            mma16816(d[0], aw[kt][0], bb);
            mma16816(d[1], aw[kt][1], bb);
            mma16816(d[2], aw[kt][2], bb);
        }
        if (tg == 0) {
#pragma unroll
            for (int g = 0; g < 3; g++) {
                spart[warp][g * 16 + qid]     = d[g][0];
                spart[warp][g * 16 + qid + 8] = d[g][2];
            }
        }
        __syncthreads();

        if (tid < IPB) {
            float ghr = 0.f, ghz = 0.f, ghn = 0.f;
#pragma unroll
            for (int w2 = 0; w2 < 16; w2++) {
                ghr += spart[w2][tid];
                ghz += spart[w2][16 + tid];
                ghn += spart[w2][32 + tid];
            }
            const int ig = b * IPB + tid;
            const float* git = g_gi + (size_t)t * GH;
            float rr = 1.0f / (1.0f + expf(-(git[ig]         + ghr + bhh[ig])));
            float zz = 1.0f / (1.0f + expf(-(git[H + ig]     + ghz + bhh[H + ig])));
            float nn = tanhf(git[2 * H + ig] + rr * (ghn + bhh[2 * H + ig]));
            float hnew = (1.0f - zz) * nn + zz * hold;
            hold = hnew;
            g_seq[t * H + ig] = hnew;
            g_hh[(1 - p) * H + ig] = __float2half(hnew);
        }
        __syncthreads();
        if (tid == 0) {
            bar_arrive(&g_bar[t]);                // release: orders the h writes
            while (bar_ld_acq(&g_bar[t]) < NBLK) {}
        }
        __syncthreads();
    }
}

// ---------------- 5) final linear ----------------
__global__ void k_final(const float* __restrict__ lw, const float* __restrict__ lb,
                        float* __restrict__ out) {
    __shared__ float s[T];
    int n = blockIdx.x, tid = threadIdx.x;   // 256 threads
    s[tid] = g_seq[tid * H + n];
    __syncthreads();
    if (tid < STEPA) {
        float a = lb[tid];
#pragma unroll 8
        for (int t = 0; t < T; t++) a = fmaf(s[t], lw[t * STEPA + tid], a);
        out[n * STEPA + tid] = a;
    }
}

// ---------------- launch ----------------
extern "C" void kernel_launch(void* const* d_in, const int* in_sizes, int n_in,
                              void* d_out, int out_size) {
    const float* x      = (const float*)d_in[0];
    const int*   ei     = (const int*)  d_in[1];
    const float* ew     = (const float*)d_in[2];
    const float* cnn_w  = (const float*)d_in[3];
    const float* cnn_b  = (const float*)d_in[4];
    const float* gcn_w  = (const float*)d_in[5];
    const float* gcn_b  = (const float*)d_in[6];
    const float* wih    = (const float*)d_in[7];
    const float* whh    = (const float*)d_in[8];
    const float* bih    = (const float*)d_in[9];
    const float* bhh    = (const float*)d_in[10];
    const float* lin_w  = (const float*)d_in[11];
    const float* lin_b  = (const float*)d_in[12];
    float* out = (float*)d_out;

    // launch #1: fused preprocessing (persistent)
    k_pre<<<NBLK, PRE_THREADS>>>(x, cnn_w, cnn_b, ei, ew, gcn_w, gcn_b);

    // 3 GRU layers: launches 2..10 (scan of layer 0 is launch #4 for ncu capture)
    for (int l = 0; l < NLAY; l++) {
        dim3 grid(GH / 128, T / 64);
        k_gi<<<grid, 256>>>(wih + (size_t)l * GH * H, bih + l * GH);
        k_zero2<<<(2 * H + 255) / 256, 256>>>();
        k_scan<<<NBLK, SCAN_THREADS>>>(whh + (size_t)l * GH * H, bhh + l * GH);
    }

    k_final<<<NNODES, T>>>(lin_w, lin_b, out);
}